// round 11
// baseline (speedup 1.0000x reference)
#include <cuda_runtime.h>
#include <math.h>

// Problem shape (fixed by dataset): B=8, T=4096, F=1024
#define B_DIM 8
#define T_DIM 4096
#define F_DIM 1024
#define F4 (F_DIM / 4)          // 256 float4 per row
#define ROWS_PER_BLK 32
#define NBLK_PER_B (T_DIM / ROWS_PER_BLK)   // 128

// Scratch (no device-memory allocations allowed). Zero-initialized at module
// load; every launch restores state to zero so graph replays are deterministic.
__device__ float g_ksum[B_DIM * F_DIM];
__device__ float g_kc[B_DIM * F_DIM];
__device__ float g_invkd[B_DIM];
__device__ int   g_len[B_DIM];
__device__ int   g_done[B_DIM];

// ---------------------------------------------------------------------------
__device__ __forceinline__ float block_reduce1(float v) {
    __shared__ float sh[8];
    #pragma unroll
    for (int o = 16; o; o >>= 1) v += __shfl_xor_sync(0xffffffffu, v, o);
    int w = threadIdx.x >> 5, l = threadIdx.x & 31;
    if (l == 0) sh[w] = v;
    __syncthreads();
    if (w == 0) {
        v = (l < 8) ? sh[l] : 0.f;
        #pragma unroll
        for (int o = 4; o; o >>= 1) v += __shfl_xor_sync(0xffffffffu, v, o);
        if (l == 0) sh[0] = v;
    }
    __syncthreads();
    float r = sh[0];
    __syncthreads();
    return r;
}

// ---------------------------------------------------------------------------
// Kernel 1: masked per-channel sum over T + per-batch stats + padded-row
// zero-fill. grid (NBLK_PER_B, B), 256 threads, 32 rows/block. Mask is a
// monotone prefix, so rows [count, 32) of this window are padding: zero-fill
// them here (evict-first stores), letting the output pass skip padding.
// Ticketed last block computes k_centered and 1/kd, restores scratch.
// x reads use __ldcg: no L1 allocation, lines parked in L2 for pass 2.
__global__ void __launch_bounds__(256) k_reduce_fused(
        const float4* __restrict__ x,
        const int* __restrict__ mask,
        float4* __restrict__ out) {
    const int b = blockIdx.y;
    const int t0 = blockIdx.x * ROWS_PER_BLK;
    const int tid = threadIdx.x;

    __shared__ int scount;
    __shared__ int slast;

    if (tid < 32) {
        int mv = mask[b * T_DIM + t0 + tid];
        unsigned bal = __ballot_sync(0xffffffffu, mv != 0);
        if (tid == 0) scount = __popc(bal);
    }
    __syncthreads();
    const int count = scount;

    const size_t rowbase = ((size_t)b * T_DIM + t0) * F4;

    if (count > 0) {
        const float4* xb = x + rowbase + tid;
        float ax = 0.f, ay = 0.f, az = 0.f, aw = 0.f;
        #pragma unroll 8
        for (int r = 0; r < count; ++r) {
            float4 v = __ldcg(&xb[(size_t)r * F4]);
            ax += v.x; ay += v.y; az += v.z; aw += v.w;
        }
        float* dst = &g_ksum[b * F_DIM + tid * 4];
        atomicAdd(dst + 0, ax);
        atomicAdd(dst + 1, ay);
        atomicAdd(dst + 2, az);
        atomicAdd(dst + 3, aw);
        if (tid == 0) atomicAdd(&g_len[b], count);
    }

    // Zero-fill this block's padded rows (rows [count, 32) of the window).
    {
        const float4 z = make_float4(0.f, 0.f, 0.f, 0.f);
        for (int r = count; r < ROWS_PER_BLK; ++r)
            __stcs(&out[rowbase + (size_t)r * F4 + tid], z);
    }

    // ---- completion ticket ----
    __threadfence();
    __syncthreads();
    if (tid == 0)
        slast = (atomicAdd(&g_done[b], 1) == NBLK_PER_B - 1) ? 1 : 0;
    __syncthreads();
    if (!slast) return;

    // ---- last block of this batch: per-batch stats ----
    const float L = (float)g_len[b];
    const float invL = 1.0f / L;

    float kv[4];
    float s = 0.f;
    #pragma unroll
    for (int j = 0; j < 4; ++j) {
        kv[j] = g_ksum[b * F_DIM + tid * 4 + j] * invL;
        s += kv[j];
    }
    float meank = block_reduce1(s) * (1.0f / (float)F_DIM);

    float ss = 0.f;
    #pragma unroll
    for (int j = 0; j < 4; ++j) {
        float kc = kv[j] - meank;
        g_kc[b * F_DIM + tid * 4 + j] = kc;
        ss += kc * kc;
        g_ksum[b * F_DIM + tid * 4 + j] = 0.0f;   // restore for next replay
    }
    float kd2 = block_reduce1(ss);
    if (tid == 0) {
        g_invkd[b] = rsqrtf(kd2);
        g_len[b] = 0;
        g_done[b] = 0;
    }
}

// ---------------------------------------------------------------------------
// Kernel 2: WARP-PER-ROW output over VALID rows only (padding already zeroed
// by kernel 1). Reverse global order for L2 reuse of the x tail. Launch
// bounds cap regs at 51 (5 blocks/SM, 40 warps) — R10's 64-reg codegen
// dropped occupancy to 42% and cost ~10% bandwidth.
__global__ void __launch_bounds__(256, 5) pfsa_out_kernel(
        const float4* __restrict__ x,
        const int* __restrict__ mask,
        float4* __restrict__ out) {
    const int warp = threadIdx.x >> 5;
    const int lane = threadIdx.x & 31;

    const int row = (B_DIM * T_DIM - 1) - (blockIdx.x * 8 + warp);
    const int b = row >> 12;            // row / T_DIM
    const int t = row & (T_DIM - 1);    // row % T_DIM

    if (!mask[b * T_DIM + t]) return;   // padding handled in kernel 1

    const size_t base = (size_t)row * F4;

    // Front-batched x loads: 8 independent float4 (last use -> .cs)
    float4 v[8];
    #pragma unroll
    for (int j = 0; j < 8; ++j) v[j] = __ldcs(&x[base + lane + j * 32]);

    float s1 = 0.f, s2 = 0.f;
    #pragma unroll
    for (int j = 0; j < 8; ++j) {
        s1 += v[j].x + v[j].y + v[j].z + v[j].w;
        s2 += v[j].x * v[j].x + v[j].y * v[j].y + v[j].z * v[j].z + v[j].w * v[j].w;
    }

    // kc dot in two 4-wide chunks (kc: 4 KB/batch, L1/L2-resident)
    const float4* kcb = (const float4*)&g_kc[b * F_DIM];
    float s3 = 0.f;
    #pragma unroll
    for (int h = 0; h < 2; ++h) {
        float4 kc[4];
        #pragma unroll
        for (int j = 0; j < 4; ++j) kc[j] = kcb[lane + (h * 4 + j) * 32];
        #pragma unroll
        for (int j = 0; j < 4; ++j) {
            const float4& w = v[h * 4 + j];
            s3 += w.x * kc[j].x + w.y * kc[j].y + w.z * kc[j].z + w.w * kc[j].w;
        }
    }

    #pragma unroll
    for (int o = 16; o; o >>= 1) {
        s1 += __shfl_xor_sync(0xffffffffu, s1, o);
        s2 += __shfl_xor_sync(0xffffffffu, s2, o);
        s3 += __shfl_xor_sync(0xffffffffu, s3, o);
    }

    float qd2 = s2 - s1 * s1 * (1.0f / (float)F_DIM);
    float C = s3 * rsqrtf(qd2) * g_invkd[b];
    float A = 1.0f / (1.0f + __expf(C));   // (1 - sigmoid(C))^ALPHA, ALPHA=1

    #pragma unroll
    for (int j = 0; j < 8; ++j) {
        v[j].x *= A; v[j].y *= A; v[j].z *= A; v[j].w *= A;
        __stcs(&out[base + lane + j * 32], v[j]);
    }
}

// ---------------------------------------------------------------------------
extern "C" void kernel_launch(void* const* d_in, const int* in_sizes, int n_in,
                              void* d_out, int out_size) {
    const float4* x = (const float4*)d_in[0];
    const int* mask = (const int*)d_in[1];
    float4* out = (float4*)d_out;

    dim3 g1(NBLK_PER_B, B_DIM);
    k_reduce_fused<<<g1, 256>>>(x, mask, out);

    pfsa_out_kernel<<<(B_DIM * T_DIM) / 8, 256>>>(x, mask, out);
}

// round 12
// speedup vs baseline: 1.0006x; 1.0006x over previous
#include <cuda_runtime.h>
#include <math.h>

// Problem shape (fixed by dataset): B=8, T=4096, F=1024
#define B_DIM 8
#define T_DIM 4096
#define F_DIM 1024
#define F4 (F_DIM / 4)          // 256 float4 per row
#define ROWS_PER_BLK 32
#define NBLK_PER_B (T_DIM / ROWS_PER_BLK)   // 128

// Scratch (no device-memory allocations allowed). Zero-initialized at module
// load; every launch restores state to zero so graph replays are deterministic.
__device__ float g_ksum[B_DIM * F_DIM];
__device__ float g_kc[B_DIM * F_DIM];
__device__ float g_invkd[B_DIM];
__device__ int   g_len[B_DIM];
__device__ int   g_done[B_DIM];

// ---------------------------------------------------------------------------
__device__ __forceinline__ float block_reduce1(float v) {
    __shared__ float sh[8];
    #pragma unroll
    for (int o = 16; o; o >>= 1) v += __shfl_xor_sync(0xffffffffu, v, o);
    int w = threadIdx.x >> 5, l = threadIdx.x & 31;
    if (l == 0) sh[w] = v;
    __syncthreads();
    if (w == 0) {
        v = (l < 8) ? sh[l] : 0.f;
        #pragma unroll
        for (int o = 4; o; o >>= 1) v += __shfl_xor_sync(0xffffffffu, v, o);
        if (l == 0) sh[0] = v;
    }
    __syncthreads();
    float r = sh[0];
    __syncthreads();
    return r;
}

// ---------------------------------------------------------------------------
// Kernel 1 (R11 version — 23.0us measured): masked per-channel sum over T +
// per-batch stats + padded-row zero-fill. grid (NBLK_PER_B, B), 256 threads,
// 32 rows/block. Mask is a monotone prefix, so rows [count, 32) of this
// window are padding: zero-fill them here (evict-first stores). x reads use
// __ldcg (no L1 allocation; lines parked in L2 for pass 2). Ticketed last
// block computes k_centered and 1/kd, restores scratch for graph replay.
__global__ void __launch_bounds__(256) k_reduce_fused(
        const float4* __restrict__ x,
        const int* __restrict__ mask,
        float4* __restrict__ out) {
    const int b = blockIdx.y;
    const int t0 = blockIdx.x * ROWS_PER_BLK;
    const int tid = threadIdx.x;

    __shared__ int scount;
    __shared__ int slast;

    if (tid < 32) {
        int mv = mask[b * T_DIM + t0 + tid];
        unsigned bal = __ballot_sync(0xffffffffu, mv != 0);
        if (tid == 0) scount = __popc(bal);
    }
    __syncthreads();
    const int count = scount;

    const size_t rowbase = ((size_t)b * T_DIM + t0) * F4;

    if (count > 0) {
        const float4* xb = x + rowbase + tid;
        float ax = 0.f, ay = 0.f, az = 0.f, aw = 0.f;
        #pragma unroll 8
        for (int r = 0; r < count; ++r) {
            float4 v = __ldcg(&xb[(size_t)r * F4]);
            ax += v.x; ay += v.y; az += v.z; aw += v.w;
        }
        float* dst = &g_ksum[b * F_DIM + tid * 4];
        atomicAdd(dst + 0, ax);
        atomicAdd(dst + 1, ay);
        atomicAdd(dst + 2, az);
        atomicAdd(dst + 3, aw);
        if (tid == 0) atomicAdd(&g_len[b], count);
    }

    // Zero-fill this block's padded rows (rows [count, 32) of the window).
    {
        const float4 z = make_float4(0.f, 0.f, 0.f, 0.f);
        for (int r = count; r < ROWS_PER_BLK; ++r)
            __stcs(&out[rowbase + (size_t)r * F4 + tid], z);
    }

    // ---- completion ticket ----
    __threadfence();
    __syncthreads();
    if (tid == 0)
        slast = (atomicAdd(&g_done[b], 1) == NBLK_PER_B - 1) ? 1 : 0;
    __syncthreads();
    if (!slast) return;

    // ---- last block of this batch: per-batch stats ----
    const float L = (float)g_len[b];
    const float invL = 1.0f / L;

    float kv[4];
    float s = 0.f;
    #pragma unroll
    for (int j = 0; j < 4; ++j) {
        kv[j] = g_ksum[b * F_DIM + tid * 4 + j] * invL;
        s += kv[j];
    }
    float meank = block_reduce1(s) * (1.0f / (float)F_DIM);

    float ss = 0.f;
    #pragma unroll
    for (int j = 0; j < 4; ++j) {
        float kc = kv[j] - meank;
        g_kc[b * F_DIM + tid * 4 + j] = kc;
        ss += kc * kc;
        g_ksum[b * F_DIM + tid * 4 + j] = 0.0f;   // restore for next replay
    }
    float kd2 = block_reduce1(ss);
    if (tid == 0) {
        g_invkd[b] = rsqrtf(kd2);
        g_len[b] = 0;
        g_done[b] = 0;
    }
}

// ---------------------------------------------------------------------------
// Kernel 2 (exact R10 version — 28.0us measured): WARP-PER-ROW output over
// VALID rows only (padding already zeroed by kernel 1). Reverse global order
// for L2 reuse of the x tail. NO register clamp: the 64-reg codegen with all
// 16 float4 live beats every capped variant (R4, R11 both regressed).
__global__ void __launch_bounds__(256) pfsa_out_kernel(
        const float4* __restrict__ x,
        const int* __restrict__ mask,
        float4* __restrict__ out) {
    const int warp = threadIdx.x >> 5;
    const int lane = threadIdx.x & 31;

    const int row = (B_DIM * T_DIM - 1) - (blockIdx.x * 8 + warp);
    const int b = row >> 12;            // row / T_DIM
    const int t = row & (T_DIM - 1);    // row % T_DIM

    if (!mask[b * T_DIM + t]) return;   // padding handled in kernel 1

    const size_t base = (size_t)row * F4;

    // Front-batched x loads: 8 independent float4 (last use -> .cs)
    float4 v[8];
    #pragma unroll
    for (int j = 0; j < 8; ++j) v[j] = __ldcs(&x[base + lane + j * 32]);

    float s1 = 0.f, s2 = 0.f;
    #pragma unroll
    for (int j = 0; j < 8; ++j) {
        s1 += v[j].x + v[j].y + v[j].z + v[j].w;
        s2 += v[j].x * v[j].x + v[j].y * v[j].y + v[j].z * v[j].z + v[j].w * v[j].w;
    }

    // kc dot in two 4-wide chunks (kc: 4 KB/batch, L1/L2-resident)
    const float4* kcb = (const float4*)&g_kc[b * F_DIM];
    float s3 = 0.f;
    #pragma unroll
    for (int h = 0; h < 2; ++h) {
        float4 kc[4];
        #pragma unroll
        for (int j = 0; j < 4; ++j) kc[j] = kcb[lane + (h * 4 + j) * 32];
        #pragma unroll
        for (int j = 0; j < 4; ++j) {
            const float4& w = v[h * 4 + j];
            s3 += w.x * kc[j].x + w.y * kc[j].y + w.z * kc[j].z + w.w * kc[j].w;
        }
    }

    #pragma unroll
    for (int o = 16; o; o >>= 1) {
        s1 += __shfl_xor_sync(0xffffffffu, s1, o);
        s2 += __shfl_xor_sync(0xffffffffu, s2, o);
        s3 += __shfl_xor_sync(0xffffffffu, s3, o);
    }

    float qd2 = s2 - s1 * s1 * (1.0f / (float)F_DIM);
    float C = s3 * rsqrtf(qd2) * g_invkd[b];
    float A = 1.0f / (1.0f + __expf(C));   // (1 - sigmoid(C))^ALPHA, ALPHA=1

    #pragma unroll
    for (int j = 0; j < 8; ++j) {
        v[j].x *= A; v[j].y *= A; v[j].z *= A; v[j].w *= A;
        __stcs(&out[base + lane + j * 32], v[j]);
    }
}

// ---------------------------------------------------------------------------
extern "C" void kernel_launch(void* const* d_in, const int* in_sizes, int n_in,
                              void* d_out, int out_size) {
    const float4* x = (const float4*)d_in[0];
    const int* mask = (const int*)d_in[1];
    float4* out = (float4*)d_out;

    dim3 g1(NBLK_PER_B, B_DIM);
    k_reduce_fused<<<g1, 256>>>(x, mask, out);

    pfsa_out_kernel<<<(B_DIM * T_DIM) / 8, 256>>>(x, mask, out);
}